// round 6
// baseline (speedup 1.0000x reference)
#include <cuda_runtime.h>

#define WIDTH  512
#define HEIGHT 512
#define ROWS   32
#define TPB    256      // 2 px/thread -> full 512-wide row

#define W0d 0.30780133
#define W1d 0.38439734
#define C1f 1.0e-4f
#define C2f 9.0e-4f

// compile-time constants -> FFMA immediate operands
#define WCf ((float)(W1d / W0d))                        // w
#define A1f ((float)( 2.0 * W0d * W0d * W0d * W0d))     // 2k^2
#define A2f ((float)( 2.0 * W0d * W0d))                 // 2k
#define A3f ((float)(-2.0 * W0d * W0d * W0d * W0d))     // -2k^2
#define A4f ((float)( W0d * W0d * W0d * W0d))           // k^2
#define A5f ((float)( W0d * W0d))                       // k
#define A6f ((float)(-(W0d * W0d * W0d * W0d)))         // -k^2

__device__ double       g_acc   = 0.0;
__device__ unsigned int g_count = 0u;

__device__ __forceinline__ float frcp(float x) {
    float r; asm("rcp.approx.f32 %0, %1;" : "=f"(r) : "f"(x)); return r;
}

// One input row -> 5 unnormalized horizontal 3-tap sums H[q*2+i]
// (q in {a, b, aa, bb, ab}) for this thread's 2 pixels.
__device__ __forceinline__ void row_h(const float* __restrict__ pa,
                                      const float* __restrict__ pb,
                                      int x0, int lane,
                                      float* __restrict__ H) {
    float2 av = *reinterpret_cast<const float2*>(pa + x0);
    float2 bv = *reinterpret_cast<const float2*>(pb + x0);

    float la = __shfl_up_sync(0xffffffffu, av.y, 1);
    float ra = __shfl_down_sync(0xffffffffu, av.x, 1);
    float lb = __shfl_up_sync(0xffffffffu, bv.y, 1);
    float rb = __shfl_down_sync(0xffffffffu, bv.x, 1);
    if (lane == 0) {
        la = (x0 > 0) ? pa[x0 - 1] : 0.f;
        lb = (x0 > 0) ? pb[x0 - 1] : 0.f;
    }
    if (lane == 31) {
        ra = (x0 + 2 < WIDTH) ? pa[x0 + 2] : 0.f;
        rb = (x0 + 2 < WIDTH) ? pb[x0 + 2] : 0.f;
    }

    float va[4] = { la, av.x, av.y, ra };
    float vb[4] = { lb, bv.x, bv.y, rb };

#pragma unroll
    for (int i = 0; i < 2; ++i) {
        H[0 + i] = fmaf(WCf, va[i + 1], va[i] + va[i + 2]);
        H[2 + i] = fmaf(WCf, vb[i + 1], vb[i] + vb[i + 2]);
    }
    float paa[4], pbb[4], pab[4];
#pragma unroll
    for (int j = 0; j < 4; ++j) {
        paa[j] = va[j] * va[j];
        pbb[j] = vb[j] * vb[j];
        pab[j] = va[j] * vb[j];
    }
#pragma unroll
    for (int i = 0; i < 2; ++i) {
        H[4 + i] = fmaf(WCf, paa[i + 1], paa[i] + paa[i + 2]);
        H[6 + i] = fmaf(WCf, pbb[i + 1], pbb[i] + pbb[i + 2]);
        H[8 + i] = fmaf(WCf, pab[i + 1], pab[i] + pab[i + 2]);
    }
}

__device__ __forceinline__ void emit2(const float* __restrict__ P1,
                                      const float* __restrict__ H,
                                      float& acc) {
#pragma unroll
    for (int i = 0; i < 2; ++i) {
        float U1  = P1[0 + i] + H[0 + i];
        float U2  = P1[2 + i] + H[2 + i];
        float S11 = P1[4 + i] + H[4 + i];
        float S22 = P1[6 + i] + H[6 + i];
        float S12 = P1[8 + i] + H[8 + i];

        float m11 = U1 * U1;
        float m22 = U2 * U2;
        float m12 = U1 * U2;
        float msum = m11 + m22;
        float ssum = S11 + S22;

        float n1 = fmaf(A1f, m12, C1f);
        float n2 = fmaf(A2f, S12, fmaf(A3f, m12, C2f));
        float d1 = fmaf(A4f, msum, C1f);
        float d2 = fmaf(A5f, ssum, fmaf(A6f, msum, C2f));

        acc = fmaf(n1 * n2, frcp(d1 * d2), acc);
    }
}

__device__ __forceinline__ void update(float* __restrict__ P1,
                                       float* __restrict__ P2,
                                       const float* __restrict__ H) {
#pragma unroll
    for (int i = 0; i < 10; ++i) {
        P1[i] = fmaf(WCf, H[i], P2[i]);
        P2[i] = H[i];
    }
}

__global__ void __launch_bounds__(TPB)
k_ssim(const float* __restrict__ A, const float* __restrict__ B,
       float* __restrict__ out, int nblocks) {
    const int plane = blockIdx.y;
    const int y0    = blockIdx.x * ROWS;
    const float* pa = A + plane * (WIDTH * HEIGHT) + y0 * WIDTH;
    const float* pb = B + plane * (WIDTH * HEIGHT) + y0 * WIDTH;

    const int t    = threadIdx.x;
    const int lane = t & 31;
    const int x0   = t << 1;

    float P1[10], P2[10], H[10];
    float acc = 0.f;

    // row y0-1 (zero above image for top strip); no emit
    if (y0 > 0) {
        row_h(pa - WIDTH, pb - WIDTH, x0, lane, H);
#pragma unroll
        for (int i = 0; i < 10; ++i) { P1[i] = WCf * H[i]; P2[i] = H[i]; }
    } else {
#pragma unroll
        for (int i = 0; i < 10; ++i) { P1[i] = 0.f; P2[i] = 0.f; }
    }

    // row y0; no emit (output row y0-1 belongs to the strip above)
    row_h(pa, pb, x0, lane, H);
    update(P1, P2, H);

    // rows y0+1 .. y0+ROWS-1 always in-bounds; emit rows y0 .. y0+ROWS-2
#pragma unroll 1
    for (int it = 1; it < ROWS; ++it) {
        pa += WIDTH; pb += WIDTH;
        row_h(pa, pb, x0, lane, H);
        emit2(P1, H, acc);
        update(P1, P2, H);
    }

    // row y0+ROWS (zero below for bottom strip); emit last output row
    if (y0 + ROWS < HEIGHT) {
        row_h(pa + WIDTH, pb + WIDTH, x0, lane, H);
    } else {
#pragma unroll
        for (int i = 0; i < 10; ++i) H[i] = 0.f;
    }
    emit2(P1, H, acc);

    // block reduction
    __shared__ float red[TPB];
    red[t] = acc;
    __syncthreads();
#pragma unroll
    for (int s = TPB / 2; s > 0; s >>= 1) {
        if (t < s) red[t] += red[t + s];
        __syncthreads();
    }

    // global reduction: last arriving block finalizes and resets state
    if (t == 0) {
        atomicAdd(&g_acc, (double)red[0]);
        __threadfence();
        unsigned prev = atomicAdd(&g_count, 1u);
        if (prev == (unsigned)(nblocks - 1)) {
            double s = atomicAdd(&g_acc, 0.0);   // serialized fresh read
            out[0] = (float)(1.0 - s);
            g_acc   = 0.0;                       // reset for next replay
            __threadfence();
            g_count = 0u;
        }
    }
}

extern "C" void kernel_launch(void* const* d_in, const int* in_sizes, int n_in,
                              void* d_out, int out_size) {
    const float* A = (const float*)d_in[0];
    const float* B = (const float*)d_in[1];
    float* out = (float*)d_out;

    const int planes = in_sizes[0] / (WIDTH * HEIGHT);   // 96
    dim3 grid(HEIGHT / ROWS, planes);                    // 16 x 96 = 1536
    k_ssim<<<grid, TPB>>>(A, B, out, grid.x * planes);
}

// round 7
// speedup vs baseline: 1.2470x; 1.2470x over previous
#include <cuda_runtime.h>

#define WIDTH  512
#define HEIGHT 512
#define ROWS   32
#define TPB    128

#define W0d 0.30780133
#define W1d 0.38439734
#define C1f 1.0e-4f
#define C2f 9.0e-4f

// compile-time constants -> FFMA immediate operands
#define WCf ((float)(W1d / W0d))                        // w
#define A1f ((float)( 2.0 * W0d * W0d * W0d * W0d))     // 2k^2
#define A2f ((float)( 2.0 * W0d * W0d))                 // 2k
#define A3f ((float)(-2.0 * W0d * W0d * W0d * W0d))     // -2k^2
#define A4f ((float)( W0d * W0d * W0d * W0d))           // k^2
#define A5f ((float)( W0d * W0d))                       // k
#define A6f ((float)(-(W0d * W0d * W0d * W0d)))         // -k^2

__device__ double       g_acc   = 0.0;
__device__ unsigned int g_count = 0u;

__device__ __forceinline__ float frcp(float x) {
    float r; asm("rcp.approx.f32 %0, %1;" : "=f"(r) : "f"(x)); return r;
}

// prefetched row data; ea/eb: left-halo for lane 0, right-halo for lane 31
struct Ld {
    float4 a4, b4;
    float  ea, eb;
};

__device__ __forceinline__ Ld load_row(const float* __restrict__ pa,
                                       const float* __restrict__ pb,
                                       int x0, int lane) {
    Ld L;
    L.a4 = *reinterpret_cast<const float4*>(pa + x0);
    L.b4 = *reinterpret_cast<const float4*>(pb + x0);
    const int  ex    = (lane == 0) ? (x0 - 1) : (x0 + 4);
    const bool valid = (lane == 0) ? (x0 > 0)
                                   : (lane == 31 && x0 + 4 < WIDTH);
    L.ea = valid ? pa[ex] : 0.f;
    L.eb = valid ? pb[ex] : 0.f;
    return L;
}

// H[q*4+i], q in {a, b, aa, bb, ab}: unnormalized horizontal 3-tap sums
__device__ __forceinline__ void compute_h(const Ld& L, int lane,
                                          float* __restrict__ H) {
    float la = __shfl_up_sync(0xffffffffu, L.a4.w, 1);
    float ra = __shfl_down_sync(0xffffffffu, L.a4.x, 1);
    float lb = __shfl_up_sync(0xffffffffu, L.b4.w, 1);
    float rb = __shfl_down_sync(0xffffffffu, L.b4.x, 1);
    if (lane == 0)  { la = L.ea; lb = L.eb; }
    if (lane == 31) { ra = L.ea; rb = L.eb; }

    float va[6] = { la, L.a4.x, L.a4.y, L.a4.z, L.a4.w, ra };
    float vb[6] = { lb, L.b4.x, L.b4.y, L.b4.z, L.b4.w, rb };

#pragma unroll
    for (int i = 0; i < 4; ++i) {
        H[0 + i] = fmaf(WCf, va[i + 1], va[i] + va[i + 2]);
        H[4 + i] = fmaf(WCf, vb[i + 1], vb[i] + vb[i + 2]);
    }
    float paa[6], pbb[6], pab[6];
#pragma unroll
    for (int j = 0; j < 6; ++j) {
        paa[j] = va[j] * va[j];
        pbb[j] = vb[j] * vb[j];
        pab[j] = va[j] * vb[j];
    }
#pragma unroll
    for (int i = 0; i < 4; ++i) {
        H[ 8 + i] = fmaf(WCf, paa[i + 1], paa[i] + paa[i + 2]);
        H[12 + i] = fmaf(WCf, pbb[i + 1], pbb[i] + pbb[i + 2]);
        H[16 + i] = fmaf(WCf, pab[i + 1], pab[i] + pab[i + 2]);
    }
}

// emit 4 px: V = P + Hn (full unnormalized separable conv)
__device__ __forceinline__ void emit4(const float* __restrict__ P,
                                      const float* __restrict__ Hn,
                                      float& acc) {
#pragma unroll
    for (int i = 0; i < 4; ++i) {
        float U1  = P[ 0 + i] + Hn[ 0 + i];
        float U2  = P[ 4 + i] + Hn[ 4 + i];
        float S11 = P[ 8 + i] + Hn[ 8 + i];
        float S22 = P[12 + i] + Hn[12 + i];
        float S12 = P[16 + i] + Hn[16 + i];

        float m11 = U1 * U1;
        float m22 = U2 * U2;
        float m12 = U1 * U2;
        float msum = m11 + m22;
        float ssum = S11 + S22;

        float n1 = fmaf(A1f, m12, C1f);
        float n2 = fmaf(A2f, S12, fmaf(A3f, m12, C2f));
        float d1 = fmaf(A4f, msum, C1f);
        float d2 = fmaf(A5f, ssum, fmaf(A6f, msum, C2f));

        acc = fmaf(n1 * n2, frcp(d1 * d2), acc);
    }
}

// P = Hprev + wc * Hcur  (partial for the NEXT output row)
__device__ __forceinline__ void mkP(float* __restrict__ P,
                                    const float* __restrict__ Hprev,
                                    const float* __restrict__ Hcur) {
#pragma unroll
    for (int i = 0; i < 20; ++i) P[i] = fmaf(WCf, Hcur[i], Hprev[i]);
}

__global__ void __launch_bounds__(TPB)
k_ssim(const float* __restrict__ A, const float* __restrict__ B,
       float* __restrict__ out, int nblocks) {
    const int plane = blockIdx.y;
    const int y0    = blockIdx.x * ROWS;
    const float* pa = A + plane * (WIDTH * HEIGHT) + y0 * WIDTH;
    const float* pb = B + plane * (WIDTH * HEIGHT) + y0 * WIDTH;

    const int t    = threadIdx.x;
    const int lane = t & 31;
    const int x0   = t << 2;

    float P[20], H0[20], H1[20];
    float acc = 0.f;
    Ld n0, n1;

    // H(y0-1) -> H0 (zero above image for top strip)
    if (y0 > 0) {
        n0 = load_row(pa - WIDTH, pb - WIDTH, x0, lane);
        compute_h(n0, lane, H0);
    } else {
#pragma unroll
        for (int i = 0; i < 20; ++i) H0[i] = 0.f;
    }

    // row y0 -> H1; prefetch row y0+1
    n1 = load_row(pa, pb, x0, lane);
    n0 = load_row(pa + WIDTH, pb + WIDTH, x0, lane);
    compute_h(n1, lane, H1);
    mkP(P, H0, H1);                 // partial for output row y0

    // rows y0+1 .. y0+30: 15 double-iterations, prefetch one row ahead
    const float* qa = pa + 2 * WIDTH;
    const float* qb = pb + 2 * WIDTH;
#pragma unroll 1
    for (int it = 0; it < 15; ++it) {
        n1 = load_row(qa, qb, x0, lane);             // row y0+2+2it
        compute_h(n0, lane, H0);                     // row y0+1+2it
        emit4(P, H0, acc);                           // emit row y0+2it
        mkP(P, H1, H0);

        n0 = load_row(qa + WIDTH, qb + WIDTH, x0, lane);  // row y0+3+2it
        compute_h(n1, lane, H1);                     // row y0+2+2it
        emit4(P, H1, acc);                           // emit row y0+1+2it
        mkP(P, H0, H1);

        qa += 2 * WIDTH; qb += 2 * WIDTH;
    }

    // row y0+31 (data already prefetched in n0)
    compute_h(n0, lane, H0);
    emit4(P, H0, acc);                               // emit row y0+30
    mkP(P, H1, H0);

    // row y0+32 (zero below image for bottom strip)
    if (y0 + ROWS < HEIGHT) {
        n1 = load_row(pa + ROWS * WIDTH, pb + ROWS * WIDTH, x0, lane);
        compute_h(n1, lane, H1);
    } else {
#pragma unroll
        for (int i = 0; i < 20; ++i) H1[i] = 0.f;
    }
    emit4(P, H1, acc);                               // emit row y0+31

    // block reduction
    __shared__ float red[TPB];
    red[t] = acc;
    __syncthreads();
#pragma unroll
    for (int s = TPB / 2; s > 0; s >>= 1) {
        if (t < s) red[t] += red[t + s];
        __syncthreads();
    }

    // global reduction: last arriving block finalizes and resets state
    if (t == 0) {
        atomicAdd(&g_acc, (double)red[0]);
        __threadfence();
        unsigned prev = atomicAdd(&g_count, 1u);
        if (prev == (unsigned)(nblocks - 1)) {
            double s = atomicAdd(&g_acc, 0.0);   // serialized fresh read
            out[0] = (float)(1.0 - s);
            g_acc   = 0.0;                       // reset for next replay
            __threadfence();
            g_count = 0u;
        }
    }
}

extern "C" void kernel_launch(void* const* d_in, const int* in_sizes, int n_in,
                              void* d_out, int out_size) {
    const float* A = (const float*)d_in[0];
    const float* B = (const float*)d_in[1];
    float* out = (float*)d_out;

    const int planes = in_sizes[0] / (WIDTH * HEIGHT);   // 96
    dim3 grid(HEIGHT / ROWS, planes);                    // 16 x 96 = 1536
    k_ssim<<<grid, TPB>>>(A, B, out, grid.x * planes);
}

// round 8
// speedup vs baseline: 1.3003x; 1.0428x over previous
#include <cuda_runtime.h>

#define WIDTH  512
#define HEIGHT 512
#define ROWS   32
#define TPB    128

#define W0d 0.30780133
#define W1d 0.38439734
#define C1f 1.0e-4f
#define C2f 9.0e-4f

// compile-time constants -> FFMA immediate operands
#define WCf ((float)(W1d / W0d))                        // w
#define A1f ((float)( 2.0 * W0d * W0d * W0d * W0d))     // 2k^2
#define A2f ((float)( 2.0 * W0d * W0d))                 // 2k
#define A3f ((float)(-2.0 * W0d * W0d * W0d * W0d))     // -2k^2
#define A4f ((float)( W0d * W0d * W0d * W0d))           // k^2
#define A5f ((float)( W0d * W0d))                       // k
#define A6f ((float)(-(W0d * W0d * W0d * W0d)))         // -k^2

__device__ double       g_acc   = 0.0;
__device__ unsigned int g_count = 0u;

__device__ __forceinline__ float frcp(float x) {
    float r; asm("rcp.approx.f32 %0, %1;" : "=f"(r) : "f"(x)); return r;
}

// prefetched row data; ea/eb: left-halo for lane 0, right-halo for lane 31
struct Ld {
    float4 a4, b4;
    float  ea, eb;
};

__device__ __forceinline__ Ld load_row(const float* __restrict__ pa,
                                       const float* __restrict__ pb,
                                       int x0, int lane) {
    Ld L;
    L.a4 = *reinterpret_cast<const float4*>(pa + x0);
    L.b4 = *reinterpret_cast<const float4*>(pb + x0);
    const int  ex    = (lane == 0) ? (x0 - 1) : (x0 + 4);
    const bool valid = (lane == 0) ? (x0 > 0)
                                   : (lane == 31 && x0 + 4 < WIDTH);
    L.ea = valid ? pa[ex] : 0.f;
    L.eb = valid ? pb[ex] : 0.f;
    return L;
}

// H[q*4+i], q in {a, b, aa, bb, ab}: unnormalized horizontal 3-tap sums.
// Quantities processed sequentially through one temp buffer to cap live regs.
__device__ __forceinline__ void compute_h(const Ld& L, int lane,
                                          float* __restrict__ H) {
    float la = __shfl_up_sync(0xffffffffu, L.a4.w, 1);
    float ra = __shfl_down_sync(0xffffffffu, L.a4.x, 1);
    float lb = __shfl_up_sync(0xffffffffu, L.b4.w, 1);
    float rb = __shfl_down_sync(0xffffffffu, L.b4.x, 1);
    if (lane == 0)  { la = L.ea; lb = L.eb; }
    if (lane == 31) { ra = L.ea; rb = L.eb; }

    float va[6] = { la, L.a4.x, L.a4.y, L.a4.z, L.a4.w, ra };
    float vb[6] = { lb, L.b4.x, L.b4.y, L.b4.z, L.b4.w, rb };

#pragma unroll
    for (int i = 0; i < 4; ++i) {
        H[0 + i] = fmaf(WCf, va[i + 1], va[i] + va[i + 2]);
        H[4 + i] = fmaf(WCf, vb[i + 1], vb[i] + vb[i + 2]);
    }
    {
        float p[6];
#pragma unroll
        for (int j = 0; j < 6; ++j) p[j] = va[j] * va[j];
#pragma unroll
        for (int i = 0; i < 4; ++i)
            H[8 + i] = fmaf(WCf, p[i + 1], p[i] + p[i + 2]);
#pragma unroll
        for (int j = 0; j < 6; ++j) p[j] = vb[j] * vb[j];
#pragma unroll
        for (int i = 0; i < 4; ++i)
            H[12 + i] = fmaf(WCf, p[i + 1], p[i] + p[i + 2]);
#pragma unroll
        for (int j = 0; j < 6; ++j) p[j] = va[j] * vb[j];
#pragma unroll
        for (int i = 0; i < 4; ++i)
            H[16 + i] = fmaf(WCf, p[i + 1], p[i] + p[i + 2]);
    }
}

// emit 4 px: V = P + Hn (full unnormalized separable conv)
__device__ __forceinline__ void emit4(const float* __restrict__ P,
                                      const float* __restrict__ Hn,
                                      float& acc) {
#pragma unroll
    for (int i = 0; i < 4; ++i) {
        float U1  = P[ 0 + i] + Hn[ 0 + i];
        float U2  = P[ 4 + i] + Hn[ 4 + i];
        float S11 = P[ 8 + i] + Hn[ 8 + i];
        float S22 = P[12 + i] + Hn[12 + i];
        float S12 = P[16 + i] + Hn[16 + i];

        float m11 = U1 * U1;
        float m22 = U2 * U2;
        float m12 = U1 * U2;
        float msum = m11 + m22;
        float ssum = S11 + S22;

        float n1 = fmaf(A1f, m12, C1f);
        float n2 = fmaf(A2f, S12, fmaf(A3f, m12, C2f));
        float d1 = fmaf(A4f, msum, C1f);
        float d2 = fmaf(A5f, ssum, fmaf(A6f, msum, C2f));

        acc = fmaf(n1 * n2, frcp(d1 * d2), acc);
    }
}

// P = Hprev + wc * Hcur  (partial for the NEXT output row)
__device__ __forceinline__ void mkP(float* __restrict__ P,
                                    const float* __restrict__ Hprev,
                                    const float* __restrict__ Hcur) {
#pragma unroll
    for (int i = 0; i < 20; ++i) P[i] = fmaf(WCf, Hcur[i], Hprev[i]);
}

__global__ void __launch_bounds__(TPB, 5)
k_ssim(const float* __restrict__ A, const float* __restrict__ B,
       float* __restrict__ out, int nblocks) {
    const int plane = blockIdx.y;
    const int y0    = blockIdx.x * ROWS;
    const float* pa = A + plane * (WIDTH * HEIGHT) + y0 * WIDTH;
    const float* pb = B + plane * (WIDTH * HEIGHT) + y0 * WIDTH;

    const int t    = threadIdx.x;
    const int lane = t & 31;
    const int x0   = t << 2;

    float P[20], H0[20], H1[20];
    float acc = 0.f;
    Ld n0, n1;

    // H(y0-1) -> H0 (zero above image for top strip)
    if (y0 > 0) {
        n0 = load_row(pa - WIDTH, pb - WIDTH, x0, lane);
        compute_h(n0, lane, H0);
    } else {
#pragma unroll
        for (int i = 0; i < 20; ++i) H0[i] = 0.f;
    }

    // row y0 -> H1; prefetch row y0+1
    n1 = load_row(pa, pb, x0, lane);
    n0 = load_row(pa + WIDTH, pb + WIDTH, x0, lane);
    compute_h(n1, lane, H1);
    mkP(P, H0, H1);                 // partial for output row y0

    // rows y0+1 .. y0+30: 15 double-iterations, prefetch one row ahead
    const float* qa = pa + 2 * WIDTH;
    const float* qb = pb + 2 * WIDTH;
#pragma unroll 1
    for (int it = 0; it < 15; ++it) {
        n1 = load_row(qa, qb, x0, lane);                  // row y0+2+2it
        compute_h(n0, lane, H0);                          // row y0+1+2it
        emit4(P, H0, acc);                                // emit row y0+2it
        mkP(P, H1, H0);

        n0 = load_row(qa + WIDTH, qb + WIDTH, x0, lane);  // row y0+3+2it
        compute_h(n1, lane, H1);                          // row y0+2+2it
        emit4(P, H1, acc);                                // emit row y0+1+2it
        mkP(P, H0, H1);

        qa += 2 * WIDTH; qb += 2 * WIDTH;
    }

    // row y0+31 (data already prefetched in n0)
    compute_h(n0, lane, H0);
    emit4(P, H0, acc);                                    // emit row y0+30
    mkP(P, H1, H0);

    // row y0+32 (zero below image for bottom strip)
    if (y0 + ROWS < HEIGHT) {
        n1 = load_row(pa + ROWS * WIDTH, pb + ROWS * WIDTH, x0, lane);
        compute_h(n1, lane, H1);
    } else {
#pragma unroll
        for (int i = 0; i < 20; ++i) H1[i] = 0.f;
    }
    emit4(P, H1, acc);                                    // emit row y0+31

    // reduction: warp shuffle, then cross-warp via smem
    __shared__ float red[4];
#pragma unroll
    for (int off = 16; off > 0; off >>= 1)
        acc += __shfl_down_sync(0xffffffffu, acc, off);
    if (lane == 0) red[t >> 5] = acc;
    __syncthreads();

    if (t == 0) {
        float s = red[0] + red[1] + red[2] + red[3];
        atomicAdd(&g_acc, (double)s);
        __threadfence();
        unsigned prev = atomicAdd(&g_count, 1u);
        if (prev == (unsigned)(nblocks - 1)) {
            double tot = atomicAdd(&g_acc, 0.0);   // serialized fresh read
            out[0] = (float)(1.0 - tot);
            g_acc   = 0.0;                         // reset for next replay
            __threadfence();
            g_count = 0u;
        }
    }
}

extern "C" void kernel_launch(void* const* d_in, const int* in_sizes, int n_in,
                              void* d_out, int out_size) {
    const float* A = (const float*)d_in[0];
    const float* B = (const float*)d_in[1];
    float* out = (float*)d_out;

    const int planes = in_sizes[0] / (WIDTH * HEIGHT);   // 96
    dim3 grid(HEIGHT / ROWS, planes);                    // 16 x 96 = 1536
    k_ssim<<<grid, TPB>>>(A, B, out, grid.x * planes);
}

// round 9
// speedup vs baseline: 1.3406x; 1.0310x over previous
#include <cuda_runtime.h>

#define WIDTH  512
#define HEIGHT 512
#define ROWS   32
#define TPB    128

#define W0d 0.30780133
#define W1d 0.38439734
#define C1f 1.0e-4f
#define C2f 9.0e-4f

// compile-time constants -> FFMA immediate operands
#define WCf ((float)(W1d / W0d))                        // w
#define A1f ((float)( 2.0 * W0d * W0d * W0d * W0d))     // 2k^2
#define A2f ((float)( 2.0 * W0d * W0d))                 // 2k
#define A3f ((float)(-2.0 * W0d * W0d * W0d * W0d))     // -2k^2
#define A4f ((float)( W0d * W0d * W0d * W0d))           // k^2
#define A5f ((float)( W0d * W0d))                       // k
#define A6f ((float)(-(W0d * W0d * W0d * W0d)))         // -k^2

__device__ double       g_acc   = 0.0;
__device__ unsigned int g_count = 0u;

__device__ __forceinline__ float frcp(float x) {
    float r; asm("rcp.approx.f32 %0, %1;" : "=f"(r) : "f"(x)); return r;
}

// prefetched row data; ea/eb: left-halo for lane 0, right-halo for lane 31
struct Ld {
    float4 a4, b4;
    float  ea, eb;
};

__device__ __forceinline__ Ld load_row(const float* __restrict__ pa,
                                       const float* __restrict__ pb,
                                       int x0, int lane) {
    Ld L;
    L.a4 = *reinterpret_cast<const float4*>(pa + x0);
    L.b4 = *reinterpret_cast<const float4*>(pb + x0);
    const int  ex    = (lane == 0) ? (x0 - 1) : (x0 + 4);
    const bool valid = (lane == 0) ? (x0 > 0)
                                   : (lane == 31 && x0 + 4 < WIDTH);
    L.ea = valid ? pa[ex] : 0.f;
    L.eb = valid ? pb[ex] : 0.f;
    return L;
}

// H[q*4+i], q in {a, b, aa, bb, ab}: unnormalized horizontal 3-tap sums.
// Quantities processed sequentially through one temp buffer to cap live regs.
__device__ __forceinline__ void compute_h(const Ld& L, int lane,
                                          float* __restrict__ H) {
    float la = __shfl_up_sync(0xffffffffu, L.a4.w, 1);
    float ra = __shfl_down_sync(0xffffffffu, L.a4.x, 1);
    float lb = __shfl_up_sync(0xffffffffu, L.b4.w, 1);
    float rb = __shfl_down_sync(0xffffffffu, L.b4.x, 1);
    if (lane == 0)  { la = L.ea; lb = L.eb; }
    if (lane == 31) { ra = L.ea; rb = L.eb; }

    float va[6] = { la, L.a4.x, L.a4.y, L.a4.z, L.a4.w, ra };
    float vb[6] = { lb, L.b4.x, L.b4.y, L.b4.z, L.b4.w, rb };

#pragma unroll
    for (int i = 0; i < 4; ++i) {
        H[0 + i] = fmaf(WCf, va[i + 1], va[i] + va[i + 2]);
        H[4 + i] = fmaf(WCf, vb[i + 1], vb[i] + vb[i + 2]);
    }
    {
        float p[6];
#pragma unroll
        for (int j = 0; j < 6; ++j) p[j] = va[j] * va[j];
#pragma unroll
        for (int i = 0; i < 4; ++i)
            H[8 + i] = fmaf(WCf, p[i + 1], p[i] + p[i + 2]);
#pragma unroll
        for (int j = 0; j < 6; ++j) p[j] = vb[j] * vb[j];
#pragma unroll
        for (int i = 0; i < 4; ++i)
            H[12 + i] = fmaf(WCf, p[i + 1], p[i] + p[i + 2]);
#pragma unroll
        for (int j = 0; j < 6; ++j) p[j] = va[j] * vb[j];
#pragma unroll
        for (int i = 0; i < 4; ++i)
            H[16 + i] = fmaf(WCf, p[i + 1], p[i] + p[i + 2]);
    }
}

// emit 4 px: V = P + Hn (full unnormalized separable conv)
__device__ __forceinline__ void emit4(const float* __restrict__ P,
                                      const float* __restrict__ Hn,
                                      float& acc) {
#pragma unroll
    for (int i = 0; i < 4; ++i) {
        float U1  = P[ 0 + i] + Hn[ 0 + i];
        float U2  = P[ 4 + i] + Hn[ 4 + i];
        float S11 = P[ 8 + i] + Hn[ 8 + i];
        float S22 = P[12 + i] + Hn[12 + i];
        float S12 = P[16 + i] + Hn[16 + i];

        float m11 = U1 * U1;
        float m22 = U2 * U2;
        float m12 = U1 * U2;
        float msum = m11 + m22;
        float ssum = S11 + S22;

        float n1 = fmaf(A1f, m12, C1f);
        float n2 = fmaf(A2f, S12, fmaf(A3f, m12, C2f));
        float d1 = fmaf(A4f, msum, C1f);
        float d2 = fmaf(A5f, ssum, fmaf(A6f, msum, C2f));

        acc = fmaf(n1 * n2, frcp(d1 * d2), acc);
    }
}

// P = Hprev + wc * Hcur  (partial for the NEXT output row)
__device__ __forceinline__ void mkP(float* __restrict__ P,
                                    const float* __restrict__ Hprev,
                                    const float* __restrict__ Hcur) {
#pragma unroll
    for (int i = 0; i < 20; ++i) P[i] = fmaf(WCf, Hcur[i], Hprev[i]);
}

__global__ void __launch_bounds__(TPB, 6)
k_ssim(const float* __restrict__ A, const float* __restrict__ B,
       float* __restrict__ out, int nblocks) {
    const int plane = blockIdx.y;
    const int y0    = blockIdx.x * ROWS;
    const float* pa = A + plane * (WIDTH * HEIGHT) + y0 * WIDTH;
    const float* pb = B + plane * (WIDTH * HEIGHT) + y0 * WIDTH;

    const int t    = threadIdx.x;
    const int lane = t & 31;
    const int x0   = t << 2;

    float P[20], H0[20], H1[20];
    float acc = 0.f;
    Ld n0, n1;

    // H(y0-1) -> H0 (zero above image for top strip)
    if (y0 > 0) {
        n0 = load_row(pa - WIDTH, pb - WIDTH, x0, lane);
        compute_h(n0, lane, H0);
    } else {
#pragma unroll
        for (int i = 0; i < 20; ++i) H0[i] = 0.f;
    }

    // row y0 -> H1; prefetch row y0+1
    n1 = load_row(pa, pb, x0, lane);
    n0 = load_row(pa + WIDTH, pb + WIDTH, x0, lane);
    compute_h(n1, lane, H1);
    mkP(P, H0, H1);                 // partial for output row y0

    // advance to row y0+2; running pointers only (epilogue reuses them)
    pa += 2 * WIDTH; pb += 2 * WIDTH;

    // rows y0+1 .. y0+30: 15 double-iterations, prefetch one row ahead
#pragma unroll 1
    for (int it = 0; it < 15; ++it) {
        n1 = load_row(pa, pb, x0, lane);                  // row y0+2+2it
        compute_h(n0, lane, H0);                          // row y0+1+2it
        emit4(P, H0, acc);                                // emit row y0+2it
        mkP(P, H1, H0);

        n0 = load_row(pa + WIDTH, pb + WIDTH, x0, lane);  // row y0+3+2it
        compute_h(n1, lane, H1);                          // row y0+2+2it
        emit4(P, H1, acc);                                // emit row y0+1+2it
        mkP(P, H0, H1);

        pa += 2 * WIDTH; pb += 2 * WIDTH;
    }
    // here pa/pb point at row y0+32

    // row y0+31 (data already prefetched in n0)
    compute_h(n0, lane, H0);
    emit4(P, H0, acc);                                    // emit row y0+30
    mkP(P, H1, H0);

    // row y0+32 (zero below image for bottom strip)
    if (y0 + ROWS < HEIGHT) {
        n1 = load_row(pa, pb, x0, lane);
        compute_h(n1, lane, H1);
    } else {
#pragma unroll
        for (int i = 0; i < 20; ++i) H1[i] = 0.f;
    }
    emit4(P, H1, acc);                                    // emit row y0+31

    // reduction: warp shuffle, then cross-warp via smem
    __shared__ float red[4];
#pragma unroll
    for (int off = 16; off > 0; off >>= 1)
        acc += __shfl_down_sync(0xffffffffu, acc, off);
    if (lane == 0) red[t >> 5] = acc;
    __syncthreads();

    if (t == 0) {
        float s = red[0] + red[1] + red[2] + red[3];
        atomicAdd(&g_acc, (double)s);
        __threadfence();
        unsigned prev = atomicAdd(&g_count, 1u);
        if (prev == (unsigned)(nblocks - 1)) {
            double tot = atomicAdd(&g_acc, 0.0);   // serialized fresh read
            out[0] = (float)(1.0 - tot);
            g_acc   = 0.0;                         // reset for next replay
            __threadfence();
            g_count = 0u;
        }
    }
}

extern "C" void kernel_launch(void* const* d_in, const int* in_sizes, int n_in,
                              void* d_out, int out_size) {
    const float* A = (const float*)d_in[0];
    const float* B = (const float*)d_in[1];
    float* out = (float*)d_out;

    const int planes = in_sizes[0] / (WIDTH * HEIGHT);   // 96
    dim3 grid(HEIGHT / ROWS, planes);                    // 16 x 96 = 1536
    k_ssim<<<grid, TPB>>>(A, B, out, grid.x * planes);
}